// round 17
// baseline (speedup 1.0000x reference)
#include <cuda_runtime.h>
#include <cuda_bf16.h>
#include <stdint.h>
#include <math.h>

#define B_    2
#define T_    2048
#define H_    8
#define DK_   64
#define DIN_  512
#define DOUT_ 512
#define BH_   (B_ * H_)

// Scratch (__device__ globals per allocation-free rule)
// Q/K: pre-split packed bf16x2 words, word order PERMUTED within 8-groups
//      (storage s(j)=2*(j&3)+(j>>2)) so mma fragment pairs are adjacent.
// V: tf32 bit patterns (unpermuted). O: tf32 bits, dk PERMUTED within 8-groups.
// Wo: tf32 bits, k-dim permuted (prep kernel).
__device__ uint32_t g_qhi[BH_ * T_ * 32];
__device__ uint32_t g_qlo[BH_ * T_ * 32];
__device__ uint32_t g_khi[BH_ * T_ * 32];
__device__ uint32_t g_klo[BH_ * T_ * 32];
__device__ uint32_t g_vh[BH_ * T_ * DK_];
__device__ uint32_t g_oh[BH_ * T_ * DK_];
__device__ uint32_t g_wo[DIN_ * DOUT_];

// ---------------------------------------------------------------------------
// helpers
// ---------------------------------------------------------------------------
__device__ __forceinline__ uint32_t f2tf(float f) {
    uint32_t u;
    asm("cvt.rna.tf32.f32 %0, %1;" : "=r"(u) : "f"(f));
    return u;
}
__device__ __forceinline__ uint4 f2tf4(float4 v) {
    uint4 u;
    u.x = f2tf(v.x); u.y = f2tf(v.y); u.z = f2tf(v.z); u.w = f2tf(v.w);
    return u;
}
// split-bf16: x = hi + lo, both bf16; pack two adjacent k-elements per word.
__device__ __forceinline__ void bsplit2x2(float x, float y,
                                          uint32_t& hw, uint32_t& lw) {
    uint16_t xh, yh, xl, yl;
    asm("cvt.rn.bf16.f32 %0, %1;" : "=h"(xh) : "f"(x));
    asm("cvt.rn.bf16.f32 %0, %1;" : "=h"(yh) : "f"(y));
    float xhf = __uint_as_float((uint32_t)xh << 16);
    float yhf = __uint_as_float((uint32_t)yh << 16);
    asm("cvt.rn.bf16.f32 %0, %1;" : "=h"(xl) : "f"(x - xhf));
    asm("cvt.rn.bf16.f32 %0, %1;" : "=h"(yl) : "f"(y - yhf));
    hw = ((uint32_t)yh << 16) | xh;
    lw = ((uint32_t)yl << 16) | xl;
}
// tf32 k8 mma
__device__ __forceinline__ void mma8(float c[4], uint32_t a0, uint32_t a1,
                                     uint32_t a2, uint32_t a3,
                                     uint32_t b0, uint32_t b1) {
    asm volatile(
        "mma.sync.aligned.m16n8k8.row.col.f32.tf32.tf32.f32 "
        "{%0,%1,%2,%3},{%4,%5,%6,%7},{%8,%9},{%0,%1,%2,%3};\n"
        : "+f"(c[0]), "+f"(c[1]), "+f"(c[2]), "+f"(c[3])
        : "r"(a0), "r"(a1), "r"(a2), "r"(a3), "r"(b0), "r"(b1));
}
// bf16 k16 mma
__device__ __forceinline__ void mma16(float c[4], uint32_t a0, uint32_t a1,
                                      uint32_t a2, uint32_t a3,
                                      uint32_t b0, uint32_t b1) {
    asm volatile(
        "mma.sync.aligned.m16n8k16.row.col.f32.bf16.bf16.f32 "
        "{%0,%1,%2,%3},{%4,%5,%6,%7},{%8,%9},{%0,%1,%2,%3};\n"
        : "+f"(c[0]), "+f"(c[1]), "+f"(c[2]), "+f"(c[3])
        : "r"(a0), "r"(a1), "r"(a2), "r"(a3), "r"(b0), "r"(b1));
}

// smem layouts (words)
#define PROJQK_SMEM_WORDS (5120 + 5120 + 2560 + 2560)   // 61440 B (unchanged)
#define PROJV_SMEM_WORDS  (9216 + 4608)                 // 55296 B (unchanged)
// outproj: XS2 2x[128][40] @0,5120 | WS2 2x[64][40] @10240,12800
#define OUTPROJ_SMEM_WORDS 15360                        // 61440 B
// attn: KH2 2x[64][40] @0 | KL2 @5120 | QLO [128][40] @10240 | VS2 2x[64][68] @15360
#define ATTN_SMEM_WORDS 24064                           // 96256 B

// ---------------------------------------------------------------------------
// Kernel 0: prep Wo -> tf32 bits, k-dim permuted within 8-groups.
// ---------------------------------------------------------------------------
__global__ void prep_wo_kernel(const float* __restrict__ Wo)
{
    int idx = blockIdx.x * 256 + threadIdx.x;     // grid covers 512*512/2
    int n = idx >> 8;                              // 2 elems per thread
    int k2 = (idx & 255) * 2;
    #pragma unroll
    for (int e = 0; e < 2; e++) {
        int k = k2 + e;
        int s = (k & ~7) | (2 * (k & 3) + ((k & 7) >> 2));
        g_wo[n * DOUT_ + s] = f2tf(Wo[n * DOUT_ + k]);
    }
}

// ---------------------------------------------------------------------------
// Kernel 1a: Q/K projection, split-bf16, double-buffered. (compute unchanged)
// Epilogue stores pre-split packed hi/lo words at PERMUTED word positions.
// ---------------------------------------------------------------------------
__global__ __launch_bounds__(256, 2) void proj_qk_kernel(
    const float* __restrict__ qx, const float* __restrict__ kx,
    const float* __restrict__ Wq, const float* __restrict__ bq,
    const float* __restrict__ Wk, const float* __restrict__ bk)
{
    extern __shared__ uint32_t smp[];

    const float *x, *W, *bias;
    uint32_t *ohi, *olo;
    if (blockIdx.z == 0) { x = qx; W = Wq; bias = bq; ohi = g_qhi; olo = g_qlo; }
    else                 { x = kx; W = Wk; bias = bk; ohi = g_khi; olo = g_klo; }

    const int tid  = threadIdx.x;
    const int lane = tid & 31, w = tid >> 5;
    const int g = lane >> 2, t4 = lane & 3;
    const int m0 = blockIdx.y * 128;
    const int n0 = blockIdx.x * 64;

    const int sr = tid >> 3;
    const int sc4 = (tid & 7) * 4;
    const int wo  = (tid & 7) * 2;

    float acc[8][4];
    #pragma unroll
    for (int i = 0; i < 8; i++)
        #pragma unroll
        for (int j = 0; j < 4; j++) acc[i][j] = 0.f;

    float4 xp[4], wp[2];
    #pragma unroll
    for (int e = 0; e < 4; e++)
        xp[e] = *(const float4*)&x[(size_t)(m0 + e * 32 + sr) * DIN_ + sc4];
    #pragma unroll
    for (int e = 0; e < 2; e++)
        wp[e] = *(const float4*)&W[(size_t)(n0 + e * 32 + sr) * DIN_ + sc4];

    {
        uint32_t* Xh = smp;
        uint32_t* Xl = smp + 5120;
        uint32_t* Wh = smp + 10240;
        uint32_t* Wl = smp + 12800;
        #pragma unroll
        for (int e = 0; e < 4; e++) {
            int r = e * 32 + sr;
            uint32_t h0, l0, h1, l1;
            bsplit2x2(xp[e].x, xp[e].y, h0, l0);
            bsplit2x2(xp[e].z, xp[e].w, h1, l1);
            *(uint2*)&Xh[r * 20 + wo] = make_uint2(h0, h1);
            *(uint2*)&Xl[r * 20 + wo] = make_uint2(l0, l1);
        }
        #pragma unroll
        for (int e = 0; e < 2; e++) {
            int r = e * 32 + sr;
            uint32_t h0, l0, h1, l1;
            bsplit2x2(wp[e].x, wp[e].y, h0, l0);
            bsplit2x2(wp[e].z, wp[e].w, h1, l1);
            *(uint2*)&Wh[r * 20 + wo] = make_uint2(h0, h1);
            *(uint2*)&Wl[r * 20 + wo] = make_uint2(l0, l1);
        }
    }

    for (int k0 = 0; k0 < DIN_; k0 += 32) {
        const int cb = (k0 >> 5) & 1;
        __syncthreads();

        const bool more = (k0 + 32 < DIN_);
        if (more) {
            #pragma unroll
            for (int e = 0; e < 4; e++)
                xp[e] = *(const float4*)&x[(size_t)(m0 + e * 32 + sr) * DIN_ + k0 + 32 + sc4];
            #pragma unroll
            for (int e = 0; e < 2; e++)
                wp[e] = *(const float4*)&W[(size_t)(n0 + e * 32 + sr) * DIN_ + k0 + 32 + sc4];
        }

        uint32_t* Xh = smp + cb * 2560;
        uint32_t* Xl = smp + 5120 + cb * 2560;
        uint32_t* Wh = smp + 10240 + cb * 1280;
        uint32_t* Wl = smp + 12800 + cb * 1280;

        uint32_t ah[2][4], al[2][4];
        const int r0 = (16 * w + g) * 20, r1 = r0 + 8 * 20;
        #pragma unroll
        for (int kc = 0; kc < 2; kc++) {
            ah[kc][0] = Xh[r0 + kc * 8 + t4];
            ah[kc][1] = Xh[r1 + kc * 8 + t4];
            ah[kc][2] = Xh[r0 + kc * 8 + t4 + 4];
            ah[kc][3] = Xh[r1 + kc * 8 + t4 + 4];
            al[kc][0] = Xl[r0 + kc * 8 + t4];
            al[kc][1] = Xl[r1 + kc * 8 + t4];
            al[kc][2] = Xl[r0 + kc * 8 + t4 + 4];
            al[kc][3] = Xl[r1 + kc * 8 + t4 + 4];
        }
        #pragma unroll
        for (int kc = 0; kc < 2; kc++) {
            uint32_t bh0[8], bh1[8];
            #pragma unroll
            for (int nc = 0; nc < 8; nc++) {
                const int br = (nc * 8 + g) * 20 + kc * 8;
                bh0[nc] = Wh[br + t4];
                bh1[nc] = Wh[br + t4 + 4];
                mma16(acc[nc], ah[kc][0], ah[kc][1], ah[kc][2], ah[kc][3],
                      bh0[nc], bh1[nc]);
            }
            #pragma unroll
            for (int nc = 0; nc < 8; nc++) {
                const int br = (nc * 8 + g) * 20 + kc * 8;
                mma16(acc[nc], ah[kc][0], ah[kc][1], ah[kc][2], ah[kc][3],
                      Wl[br + t4], Wl[br + t4 + 4]);
            }
            #pragma unroll
            for (int nc = 0; nc < 8; nc++)
                mma16(acc[nc], al[kc][0], al[kc][1], al[kc][2], al[kc][3],
                      bh0[nc], bh1[nc]);
        }

        if (more) {
            uint32_t* Xh2 = smp + (cb ^ 1) * 2560;
            uint32_t* Xl2 = smp + 5120 + (cb ^ 1) * 2560;
            uint32_t* Wh2 = smp + 10240 + (cb ^ 1) * 1280;
            uint32_t* Wl2 = smp + 12800 + (cb ^ 1) * 1280;
            #pragma unroll
            for (int e = 0; e < 4; e++) {
                int r = e * 32 + sr;
                uint32_t h0, l0, h1, l1;
                bsplit2x2(xp[e].x, xp[e].y, h0, l0);
                bsplit2x2(xp[e].z, xp[e].w, h1, l1);
                *(uint2*)&Xh2[r * 20 + wo] = make_uint2(h0, h1);
                *(uint2*)&Xl2[r * 20 + wo] = make_uint2(l0, l1);
            }
            #pragma unroll
            for (int e = 0; e < 2; e++) {
                int r = e * 32 + sr;
                uint32_t h0, l0, h1, l1;
                bsplit2x2(wp[e].x, wp[e].y, h0, l0);
                bsplit2x2(wp[e].z, wp[e].w, h1, l1);
                *(uint2*)&Wh2[r * 20 + wo] = make_uint2(h0, h1);
                *(uint2*)&Wl2[r * 20 + wo] = make_uint2(l0, l1);
            }
        }
    }

    // Epilogue: bias, split, store at PERMUTED word slot so attention frag
    // pairs are adjacent: logical word nc*4+t4 -> (nc>>1)*8 + 2*t4 + (nc&1).
    const int h = n0 >> 6;
    const int mA = m0 + 16 * w + g;
    const int bA = mA >> 11, tA = mA & (T_ - 1);
    const int mBr = mA + 8;
    const int bB = mBr >> 11, tB = mBr & (T_ - 1);
    const size_t rowAo = ((size_t)(bA * H_ + h) * T_ + tA) * 32;
    const size_t rowBo = ((size_t)(bB * H_ + h) * T_ + tB) * 32;
    #pragma unroll
    for (int nc = 0; nc < 8; nc++) {
        int col = nc * 8 + 2 * t4;
        int colw = (nc >> 1) * 8 + 2 * t4 + (nc & 1);
        float bx = bias[n0 + col], by = bias[n0 + col + 1];
        uint32_t hw, lw;
        bsplit2x2(acc[nc][0] + bx, acc[nc][1] + by, hw, lw);
        ohi[rowAo + colw] = hw; olo[rowAo + colw] = lw;
        bsplit2x2(acc[nc][2] + bx, acc[nc][3] + by, hw, lw);
        ohi[rowBo + colw] = hw; olo[rowBo + colw] = lw;
    }
}

// ---------------------------------------------------------------------------
// Kernel 1b: V projection, single tf32, double-buffered. (unchanged)
// ---------------------------------------------------------------------------
__global__ __launch_bounds__(256, 2) void proj_v_kernel(
    const float* __restrict__ vx,
    const float* __restrict__ Wv, const float* __restrict__ bv)
{
    extern __shared__ uint32_t smv[];

    const int tid  = threadIdx.x;
    const int lane = tid & 31, w = tid >> 5;
    const int g = lane >> 2, t4 = lane & 3;
    const int m0 = blockIdx.y * 128;
    const int n0 = blockIdx.x * 64;

    const int sr = tid >> 3;
    const int sc4 = (tid & 7) * 4;

    float acc[8][4];
    #pragma unroll
    for (int i = 0; i < 8; i++)
        #pragma unroll
        for (int j = 0; j < 4; j++) acc[i][j] = 0.f;

    float4 xp[4], wp[2];
    #pragma unroll
    for (int e = 0; e < 4; e++)
        xp[e] = *(const float4*)&vx[(size_t)(m0 + e * 32 + sr) * DIN_ + sc4];
    #pragma unroll
    for (int e = 0; e < 2; e++)
        wp[e] = *(const float4*)&Wv[(size_t)(n0 + e * 32 + sr) * DIN_ + sc4];

    {
        uint32_t* Xs = smv;
        uint32_t* Ws = smv + 9216;
        #pragma unroll
        for (int e = 0; e < 4; e++)
            *(uint4*)&Xs[(e * 32 + sr) * 36 + sc4] = f2tf4(xp[e]);
        #pragma unroll
        for (int e = 0; e < 2; e++)
            *(uint4*)&Ws[(e * 32 + sr) * 36 + sc4] = f2tf4(wp[e]);
    }

    for (int k0 = 0; k0 < DIN_; k0 += 32) {
        const int cb = (k0 >> 5) & 1;
        __syncthreads();
        const bool more = (k0 + 32 < DIN_);
        if (more) {
            #pragma unroll
            for (int e = 0; e < 4; e++)
                xp[e] = *(const float4*)&vx[(size_t)(m0 + e * 32 + sr) * DIN_ + k0 + 32 + sc4];
            #pragma unroll
            for (int e = 0; e < 2; e++)
                wp[e] = *(const float4*)&Wv[(size_t)(n0 + e * 32 + sr) * DIN_ + k0 + 32 + sc4];
        }

        uint32_t* Xs = smv + cb * 4608;
        uint32_t* Ws = smv + 9216 + cb * 2304;

        uint32_t a[4][4];
        const int r0 = (16 * w + g) * 36, r1 = r0 + 8 * 36;
        #pragma unroll
        for (int kc = 0; kc < 4; kc++) {
            a[kc][0] = Xs[r0 + kc * 8 + t4];
            a[kc][1] = Xs[r1 + kc * 8 + t4];
            a[kc][2] = Xs[r0 + kc * 8 + t4 + 4];
            a[kc][3] = Xs[r1 + kc * 8 + t4 + 4];
        }
        #pragma unroll
        for (int kc = 0; kc < 4; kc++) {
            #pragma unroll
            for (int nc = 0; nc < 8; nc++) {
                const int br = (nc * 8 + g) * 36 + kc * 8;
                mma8(acc[nc], a[kc][0], a[kc][1], a[kc][2], a[kc][3],
                     Ws[br + t4], Ws[br + t4 + 4]);
            }
        }

        if (more) {
            uint32_t* Xs2 = smv + (cb ^ 1) * 4608;
            uint32_t* Ws2 = smv + 9216 + (cb ^ 1) * 2304;
            #pragma unroll
            for (int e = 0; e < 4; e++)
                *(uint4*)&Xs2[(e * 32 + sr) * 36 + sc4] = f2tf4(xp[e]);
            #pragma unroll
            for (int e = 0; e < 2; e++)
                *(uint4*)&Ws2[(e * 32 + sr) * 36 + sc4] = f2tf4(wp[e]);
        }
    }

    const int h = n0 >> 6;
    const int mA = m0 + 16 * w + g;
    const int bA = mA >> 11, tA = mA & (T_ - 1);
    const int mBr = mA + 8;
    const int bB = mBr >> 11, tB = mBr & (T_ - 1);
    uint32_t* rowA = g_vh + ((size_t)(bA * H_ + h) * T_ + tA) * DK_;
    uint32_t* rowB = g_vh + ((size_t)(bB * H_ + h) * T_ + tB) * DK_;
    #pragma unroll
    for (int nc = 0; nc < 8; nc++) {
        int col = nc * 8 + 2 * t4;
        float bx = bv[n0 + col], by = bv[n0 + col + 1];
        rowA[col]     = f2tf(acc[nc][0] + bx);
        rowA[col + 1] = f2tf(acc[nc][1] + by);
        rowB[col]     = f2tf(acc[nc][2] + bx);
        rowB[col + 1] = f2tf(acc[nc][3] + by);
    }
}

// ---------------------------------------------------------------------------
// Kernel 2: attention. Q/K word-permuted in gmem -> all Q/K fragment loads
// are LDS.64 (stride 40 for bank-conflict-free pairs). Math identical.
// ---------------------------------------------------------------------------
__global__ __launch_bounds__(256, 2) void attn_kernel()
{
    extern __shared__ uint32_t sma[];
    // KH2 @0 (2x2560) | KL2 @5120 (2x2560) | QLO @10240 ([128][40]) |
    // VS2 @15360 (2x4352, stride 68)
    uint32_t* Qlo = sma + 10240;
    uint32_t* Qst = sma;                  // Q-hi staging aliases KH2 (5120 words)

    const int bh = blockIdx.x;
    const int q0 = blockIdx.y * 128;
    const uint32_t* qhiw = g_qhi + (size_t)bh * T_ * 32;
    const uint32_t* qlow = g_qlo + (size_t)bh * T_ * 32;
    const uint32_t* khiw = g_khi + (size_t)bh * T_ * 32;
    const uint32_t* klow = g_klo + (size_t)bh * T_ * 32;
    const uint32_t* vh = g_vh + (size_t)bh * T_ * DK_;
    uint32_t* oh = g_oh + (size_t)bh * T_ * DK_;

    const int tid  = threadIdx.x;
    const int lane = tid & 31, w = tid >> 5;
    const int g = lane >> 2, t4 = lane & 3;
    const int kw8 = (tid & 7) * 4;

    // ---- stage Q (pure copy of pre-split, pre-permuted words) ----
    #pragma unroll
    for (int e = 0; e < 4; e++) {
        int idx = e * 256 + tid;
        int r = idx >> 3, w8 = (idx & 7) * 4;
        *(uint4*)&Qst[r * 40 + w8] = *(const uint4*)&qhiw[(size_t)(q0 + r) * 32 + w8];
        *(uint4*)&Qlo[r * 40 + w8] = *(const uint4*)&qlow[(size_t)(q0 + r) * 32 + w8];
    }
    __syncthreads();
    const int r0q = (16 * w + g) * 40, r1q = r0q + 8 * 40;
    uint2 qh0[4], qh1[4];                  // [dc]: rows r0q/r1q, logical (t4,t4+4)
    #pragma unroll
    for (int dc = 0; dc < 4; dc++) {
        qh0[dc] = *(const uint2*)&Qst[r0q + dc * 8 + 2 * t4];
        qh1[dc] = *(const uint2*)&Qst[r1q + dc * 8 + 2 * t4];
    }
    __syncthreads();   // all frags extracted before K overwrites Q-hi staging

    // ---- pass A: Z only ----
    float z0 = 0.f, z1 = 0.f;
    uint4 kph[2], kpl[2];
    #pragma unroll
    for (int e = 0; e < 2; e++) {
        int r = (e * 256 + tid) >> 3;
        kph[e] = *(const uint4*)&khiw[(size_t)r * 32 + kw8];
        kpl[e] = *(const uint4*)&klow[(size_t)r * 32 + kw8];
    }
    #pragma unroll
    for (int e = 0; e < 2; e++) {
        int r = (e * 256 + tid) >> 3;
        *(uint4*)&sma[r * 40 + kw8]        = kph[e];
        *(uint4*)&sma[5120 + r * 40 + kw8] = kpl[e];
    }

    for (int kt = 0; kt < T_ / 64; kt++) {
        const int j0 = kt * 64;
        const int cb = kt & 1;
        __syncthreads();
        const bool more = (kt + 1 < T_ / 64);
        if (more) {
            #pragma unroll
            for (int e = 0; e < 2; e++) {
                int r = (e * 256 + tid) >> 3;
                kph[e] = *(const uint4*)&khiw[(size_t)(j0 + 64 + r) * 32 + kw8];
                kpl[e] = *(const uint4*)&klow[(size_t)(j0 + 64 + r) * 32 + kw8];
            }
        }
        uint32_t* Kh = sma + cb * 2560;
        uint32_t* Kl = sma + 5120 + cb * 2560;

        float c[8][4];
        #pragma unroll
        for (int i = 0; i < 8; i++)
            #pragma unroll
            for (int j = 0; j < 4; j++) c[i][j] = 0.f;

        #pragma unroll
        for (int dc = 0; dc < 4; dc++) {
            uint2 ql0 = *(const uint2*)&Qlo[r0q + dc * 8 + 2 * t4];
            uint2 ql1 = *(const uint2*)&Qlo[r1q + dc * 8 + 2 * t4];
            uint2 bhv[8];
            #pragma unroll
            for (int kc = 0; kc < 8; kc++) {
                bhv[kc] = *(const uint2*)&Kh[(kc * 8 + g) * 40 + dc * 8 + 2 * t4];
                mma16(c[kc], qh0[dc].x, qh1[dc].x, qh0[dc].y, qh1[dc].y,
                      bhv[kc].x, bhv[kc].y);                     // hi*hi
            }
            #pragma unroll
            for (int kc = 0; kc < 8; kc++) {
                uint2 blv = *(const uint2*)&Kl[(kc * 8 + g) * 40 + dc * 8 + 2 * t4];
                mma16(c[kc], qh0[dc].x, qh1[dc].x, qh0[dc].y, qh1[dc].y,
                      blv.x, blv.y);                             // hi*lo
            }
            #pragma unroll
            for (int kc = 0; kc < 8; kc++)
                mma16(c[kc], ql0.x, ql1.x, ql0.y, ql1.y,
                      bhv[kc].x, bhv[kc].y);                     // lo*hi
        }

        #pragma unroll
        for (int kc = 0; kc < 8; kc++) {
            z0 += __expf(c[kc][0]) + __expf(c[kc][1]);
            z1 += __expf(c[kc][2]) + __expf(c[kc][3]);
        }

        if (more) {
            uint32_t* Kh2 = sma + (cb ^ 1) * 2560;
            uint32_t* Kl2 = sma + 5120 + (cb ^ 1) * 2560;
            #pragma unroll
            for (int e = 0; e < 2; e++) {
                int r = (e * 256 + tid) >> 3;
                *(uint4*)&Kh2[r * 40 + kw8] = kph[e];
                *(uint4*)&Kl2[r * 40 + kw8] = kpl[e];
            }
        }
    }
    z0 += __shfl_xor_sync(0xffffffffu, z0, 1);
    z0 += __shfl_xor_sync(0xffffffffu, z0, 2);
    z1 += __shfl_xor_sync(0xffffffffu, z1, 1);
    z1 += __shfl_xor_sync(0xffffffffu, z1, 2);
    const float thr0 = z0 * (1.0f / (float)T_), inv0 = 1.0f / z0;
    const float thr1 = z1 * (1.0f / (float)T_), inv1 = 1.0f / z1;

    // ---- pass B: recompute S (bit-identical), threshold, PV ----
    float o[8][4];
    #pragma unroll
    for (int i = 0; i < 8; i++)
        #pragma unroll
        for (int j = 0; j < 4; j++) o[i][j] = 0.f;

    const int vsr = tid >> 4;
    const int vsc4 = (tid & 15) * 4;
    uint4 vp[4];
    #pragma unroll
    for (int e = 0; e < 4; e++)
        vp[e] = *(const uint4*)&vh[(size_t)(e * 16 + vsr) * DK_ + vsc4];
    #pragma unroll
    for (int e = 0; e < 2; e++) {
        int r = (e * 256 + tid) >> 3;
        kph[e] = *(const uint4*)&khiw[(size_t)r * 32 + kw8];
        kpl[e] = *(const uint4*)&klow[(size_t)r * 32 + kw8];
    }
    __syncthreads();   // pass-A reads of K buffers complete everywhere
    #pragma unroll
    for (int e = 0; e < 2; e++) {
        int r = (e * 256 + tid) >> 3;
        *(uint4*)&sma[r * 40 + kw8]        = kph[e];
        *(uint4*)&sma[5120 + r * 40 + kw8] = kpl[e];
    }
    #pragma unroll
    for (int e = 0; e < 4; e++)
        *(uint4*)&sma[15360 + (e * 16 + vsr) * 68 + vsc4] = vp[e];

    const int srcA = (lane & ~3) | (t4 >> 1);
    const int srcB = srcA + 2;
    const bool odd = (t4 & 1) != 0;

    for (int kt = 0; kt < T_ / 64; kt++) {
        const int j0 = kt * 64;
        const int cb = kt & 1;
        __syncthreads();
        const bool more = (kt + 1 < T_ / 64);
        if (more) {
            #pragma unroll
            for (int e = 0; e < 2; e++) {
                int r = (e * 256 + tid) >> 3;
                kph[e] = *(const uint4*)&khiw[(size_t)(j0 + 64 + r) * 32 + kw8];
                kpl[e] = *(const uint4*)&klow[(size_t)(j0 + 64 + r) * 32 + kw8];
            }
            #pragma unroll
            for (int e = 0; e < 4; e++)
                vp[e] = *(const uint4*)&vh[(size_t)(j0 + 64 + e * 16 + vsr) * DK_ + vsc4];
        }
        uint32_t* Kh = sma + cb * 2560;
        uint32_t* Kl = sma + 5120 + cb * 2560;
        uint32_t* Vs = sma + 15360 + cb * 4352;

        #pragma unroll
        for (int kcg = 0; kcg < 2; kcg++) {
            float c[4][4];
            #pragma unroll
            for (int i = 0; i < 4; i++)
                #pragma unroll
                for (int j = 0; j < 4; j++) c[i][j] = 0.f;

            #pragma unroll
            for (int dc = 0; dc < 4; dc++) {
                uint2 ql0 = *(const uint2*)&Qlo[r0q + dc * 8 + 2 * t4];
                uint2 ql1 = *(const uint2*)&Qlo[r1q + dc * 8 + 2 * t4];
                uint2 bhv[4];
                #pragma unroll
                for (int k2 = 0; k2 < 4; k2++) {
                    const int br = ((kcg * 4 + k2) * 8 + g) * 40 + dc * 8;
                    bhv[k2] = *(const uint2*)&Kh[br + 2 * t4];
                    mma16(c[k2], qh0[dc].x, qh1[dc].x, qh0[dc].y, qh1[dc].y,
                          bhv[k2].x, bhv[k2].y);                 // hi*hi
                }
                #pragma unroll
                for (int k2 = 0; k2 < 4; k2++) {
                    const int br = ((kcg * 4 + k2) * 8 + g) * 40 + dc * 8;
                    uint2 blv = *(const uint2*)&Kl[br + 2 * t4];
                    mma16(c[k2], qh0[dc].x, qh1[dc].x, qh0[dc].y, qh1[dc].y,
                          blv.x, blv.y);                         // hi*lo
                }
                #pragma unroll
                for (int k2 = 0; k2 < 4; k2++)
                    mma16(c[k2], ql0.x, ql1.x, ql0.y, ql1.y,
                          bhv[k2].x, bhv[k2].y);                 // lo*hi
            }

            #pragma unroll
            for (int k2 = 0; k2 < 4; k2++) {
                const int kc = kcg * 4 + k2;
                float w0 = __expf(c[k2][0]); w0 = (w0 > thr0) ? w0 : 0.f;
                float w1 = __expf(c[k2][1]); w1 = (w1 > thr0) ? w1 : 0.f;
                float w2 = __expf(c[k2][2]); w2 = (w2 > thr1) ? w2 : 0.f;
                float w3 = __expf(c[k2][3]); w3 = (w3 > thr1) ? w3 : 0.f;

                float v00 = __shfl_sync(0xffffffffu, w0, srcA);
                float v01 = __shfl_sync(0xffffffffu, w1, srcA);
                float v20 = __shfl_sync(0xffffffffu, w2, srcA);
                float v21 = __shfl_sync(0xffffffffu, w3, srcA);
                float u00 = __shfl_sync(0xffffffffu, w0, srcB);
                float u01 = __shfl_sync(0xffffffffu, w1, srcB);
                float u20 = __shfl_sync(0xffffffffu, w2, srcB);
                float u21 = __shfl_sync(0xffffffffu, w3, srcB);
                uint32_t pa0 = f2tf(odd ? v01 : v00);
                uint32_t pa1 = f2tf(odd ? v21 : v20);
                uint32_t pa2 = f2tf(odd ? u01 : u00);
                uint32_t pa3 = f2tf(odd ? u21 : u20);

                const int vr0 = (kc * 8 + t4) * 68;
                const int vr1 = vr0 + 4 * 68;
                #pragma unroll
                for (int dn = 0; dn < 8; dn++) {
                    uint32_t b0 = Vs[vr0 + dn * 8 + g];
                    uint32_t b1 = Vs[vr1 + dn * 8 + g];
                    mma8(o[dn], pa0, pa1, pa2, pa3, b0, b1);
                }
            }
        }

        if (more) {
            uint32_t* Kh2 = sma + (cb ^ 1) * 2560;
            uint32_t* Kl2 = sma + 5120 + (cb ^ 1) * 2560;
            uint32_t* Vs2 = sma + 15360 + (cb ^ 1) * 4352;
            #pragma unroll
            for (int e = 0; e < 2; e++) {
                int r = (e * 256 + tid) >> 3;
                *(uint4*)&Kh2[r * 40 + kw8] = kph[e];
                *(uint4*)&Kl2[r * 40 + kw8] = kpl[e];
            }
            #pragma unroll
            for (int e = 0; e < 4; e++)
                *(uint4*)&Vs2[(e * 16 + vsr) * 68 + vsc4] = vp[e];
        }
    }

    // epilogue: scale by 1/Z, store TF32 bits at PERMUTED dk positions so
    // outproj A-frag pairs are adjacent: s(j) = 2*(j&3) + ((j&7)>>2).
    uint32_t* rowA = oh + (size_t)(q0 + 16 * w + g) * DK_;
    uint32_t* rowB = rowA + 8 * DK_;
    #pragma unroll
    for (int dn = 0; dn < 8; dn++) {
        int col = dn * 8 + 2 * t4;
        int j0w = col & 7, j1w = (col + 1) & 7;
        int s0 = (col & ~7) | (2 * (j0w & 3) + (j0w >> 2));
        int s1 = (col & ~7) | (2 * (j1w & 3) + (j1w >> 2));
        rowA[s0] = f2tf(o[dn][0] * inv0);
        rowA[s1] = f2tf(o[dn][1] * inv0);
        rowB[s0] = f2tf(o[dn][2] * inv1);
        rowB[s1] = f2tf(o[dn][3] * inv1);
    }
}

// ---------------------------------------------------------------------------
// Kernel 3: output projection. A (g_oh) and B (g_wo) both k-permuted in gmem:
// staging is pure copy, all fragment loads LDS.64 (stride 40).
// ---------------------------------------------------------------------------
__global__ __launch_bounds__(256, 2) void outproj_kernel(
    const float* __restrict__ bo, float* __restrict__ out)
{
    extern __shared__ uint32_t smo[];

    const int tid  = threadIdx.x;
    const int lane = tid & 31, w = tid >> 5;
    const int g = lane >> 2, t4 = lane & 3;
    const int m0 = blockIdx.y * 128;
    const int n0 = blockIdx.x * 64;

    const int sr = tid >> 3;
    const int sc4 = (tid & 7) * 4;

    float acc[8][4];
    #pragma unroll
    for (int i = 0; i < 8; i++)
        #pragma unroll
        for (int j = 0; j < 4; j++) acc[i][j] = 0.f;

    auto xaddr = [&](int k0, int e) -> const uint4* {
        int r = e * 32 + sr;
        int m = m0 + r, bb = m >> 11, t = m & (T_ - 1);
        int kg = k0 + sc4, h = kg >> 6, dk = kg & 63;
        return (const uint4*)&g_oh[((size_t)(bb * H_ + h) * T_ + t) * DK_ + dk];
    };

    uint4 xp[4], wp[2];
    #pragma unroll
    for (int e = 0; e < 4; e++) xp[e] = *xaddr(0, e);
    #pragma unroll
    for (int e = 0; e < 2; e++)
        wp[e] = *(const uint4*)&g_wo[(size_t)(n0 + e * 32 + sr) * DOUT_ + sc4];

    {
        uint32_t* Xs = smo;
        uint32_t* Ws = smo + 10240;
        #pragma unroll
        for (int e = 0; e < 4; e++)
            *(uint4*)&Xs[(e * 32 + sr) * 40 + sc4] = xp[e];
        #pragma unroll
        for (int e = 0; e < 2; e++)
            *(uint4*)&Ws[(e * 32 + sr) * 40 + sc4] = wp[e];
    }

    for (int k0 = 0; k0 < DOUT_; k0 += 32) {
        const int cb = (k0 >> 5) & 1;
        __syncthreads();
        const bool more = (k0 + 32 < DOUT_);
        if (more) {
            #pragma unroll
            for (int e = 0; e < 4; e++) xp[e] = *xaddr(k0 + 32, e);
            #pragma unroll
            for (int e = 0; e < 2; e++)
                wp[e] = *(const uint4*)&g_wo[(size_t)(n0 + e * 32 + sr) * DOUT_ + k0 + 32 + sc4];
        }

        uint32_t* Xs = smo + cb * 5120;
        uint32_t* Ws = smo + 10240 + cb * 2560;

        uint2 a0[4], a1[4];
        const int r0 = (16 * w + g) * 40, r1 = r0 + 8 * 40;
        #pragma unroll
        for (int kc = 0; kc < 4; kc++) {
            a0[kc] = *(const uint2*)&Xs[r0 + kc * 8 + 2 * t4];
            a1[kc] = *(const uint2*)&Xs[r1 + kc * 8 + 2 * t4];
        }
        #pragma unroll
        for (int kc = 0; kc < 4; kc++) {
            #pragma unroll
            for (int nc = 0; nc < 8; nc++) {
                uint2 bv = *(const uint2*)&Ws[(nc * 8 + g) * 40 + kc * 8 + 2 * t4];
                mma8(acc[nc], a0[kc].x, a1[kc].x, a0[kc].y, a1[kc].y,
                     bv.x, bv.y);
            }
        }

        if (more) {
            uint32_t* Xs2 = smo + (cb ^ 1) * 5120;
            uint32_t* Ws2 = smo + 10240 + (cb ^ 1) * 2560;
            #pragma unroll
            for (int e = 0; e < 4; e++)
                *(uint4*)&Xs2[(e * 32 + sr) * 40 + sc4] = xp[e];
            #pragma unroll
            for (int e = 0; e < 2; e++)
                *(uint4*)&Ws2[(e * 32 + sr) * 40 + sc4] = wp[e];
        }
    }

    const int mA = m0 + 16 * w + g;
    float* rowA = out + (size_t)mA * DIN_ + n0;
    float* rowB = rowA + 8 * DIN_;
    #pragma unroll
    for (int nc = 0; nc < 8; nc++) {
        int col = nc * 8 + 2 * t4;
        float bx = bo[n0 + col], by = bo[n0 + col + 1];
        *(float2*)&rowA[col] = make_float2(acc[nc][0] + bx, acc[nc][1] + by);
        *(float2*)&rowB[col] = make_float2(acc[nc][2] + bx, acc[nc][3] + by);
    }
}

// ---------------------------------------------------------------------------
extern "C" void kernel_launch(void* const* d_in, const int* in_sizes, int n_in,
                              void* d_out, int out_size)
{
    const float* q  = (const float*)d_in[0];
    const float* k  = (const float*)d_in[1];
    const float* v  = (const float*)d_in[2];
    const float* Wq = (const float*)d_in[3];
    const float* bq = (const float*)d_in[4];
    const float* Wk = (const float*)d_in[5];
    const float* bk = (const float*)d_in[6];
    const float* Wv = (const float*)d_in[7];
    const float* bv = (const float*)d_in[8];
    const float* Wo = (const float*)d_in[9];
    const float* bo = (const float*)d_in[10];
    float* out = (float*)d_out;

    cudaFuncSetAttribute(proj_qk_kernel,
        cudaFuncAttributeMaxDynamicSharedMemorySize, PROJQK_SMEM_WORDS * 4);
    cudaFuncSetAttribute(proj_v_kernel,
        cudaFuncAttributeMaxDynamicSharedMemorySize, PROJV_SMEM_WORDS * 4);
    cudaFuncSetAttribute(attn_kernel,
        cudaFuncAttributeMaxDynamicSharedMemorySize, ATTN_SMEM_WORDS * 4);
    cudaFuncSetAttribute(outproj_kernel,
        cudaFuncAttributeMaxDynamicSharedMemorySize, OUTPROJ_SMEM_WORDS * 4);

    prep_wo_kernel<<<512, 256>>>(Wo);   // 512*256*2 = 262144 elems

    proj_qk_kernel<<<dim3(DOUT_ / 64, (B_ * T_) / 128, 2), 256,
                     PROJQK_SMEM_WORDS * 4>>>(q, k, Wq, bq, Wk, bk);
    proj_v_kernel<<<dim3(DOUT_ / 64, (B_ * T_) / 128), 256,
                    PROJV_SMEM_WORDS * 4>>>(v, Wv, bv);

    attn_kernel<<<dim3(BH_, T_ / 128), 256, ATTN_SMEM_WORDS * 4>>>();

    outproj_kernel<<<dim3(DIN_ / 64, (B_ * T_) / 128), 256,
                     OUTPROJ_SMEM_WORDS * 4>>>(bo, out);
}